// round 8
// baseline (speedup 1.0000x reference)
#include <cuda_runtime.h>
#include <cstdint>

#define NN     20000
#define KO     32
#define MTILE  64
#define KTILE  32
#define NTILES 625          // 20000/32 exact
#define GRID1  313          // ceil(20000/64)

#define APADF  36                     // A smem row stride (floats)
#define XPAD2  36                     // X smem row stride (uint2 pairs)
#define A_BYTES (MTILE * APADF * 4)   // 9216
#define X_BYTES (KTILE * XPAD2 * 8)   // 9216
#define STAGEB  (A_BYTES + X_BYTES)   // 18432
#define NSTAGE  3
#define W_OFF   (STAGEB * NSTAGE)     // 55296
#define SMEM_TOTAL (W_OFF + 4096)     // 59392

// ---- scratch (no allocations allowed) ----
__device__ __align__(16) uint2 g_X2 [NN * KO];      // X pre-split: (tf32_hi, tf32_lo)
__device__ __align__(16) float g_H2 [NN * KO];
__device__ __align__(16) float g_part[GRID1 * KO];
__device__ __align__(16) float g_psq [GRID1 * KO];
__device__ float g_scale[KO];
__device__ float g_shift[KO];

// ================= helpers =================
__device__ __forceinline__ uint32_t smem_u32(const void* p) {
    uint32_t a;
    asm("{ .reg .u64 t; cvta.to.shared.u64 t, %1; cvt.u32.u64 %0, t; }" : "=r"(a) : "l"(p));
    return a;
}
__device__ __forceinline__ void cp16(uint32_t dst, const void* src, bool ok) {
    asm volatile("cp.async.cg.shared.global [%0], [%1], 16, %2;"
                 :: "r"(dst), "l"(src), "r"(ok ? 16u : 0u) : "memory");
}
#define CP_COMMIT() asm volatile("cp.async.commit_group;" ::: "memory")
#define CP_WAIT2()  asm volatile("cp.async.wait_group 2;" ::: "memory")
#define CP_WAIT0()  asm volatile("cp.async.wait_group 0;" ::: "memory")

__device__ __forceinline__ void cvt3(float a, uint32_t& hi, uint32_t& lo) {
    asm("cvt.rna.tf32.f32 %0, %1;" : "=r"(hi) : "f"(a));
    float r = a - __uint_as_float(hi);
    asm("cvt.rna.tf32.f32 %0, %1;" : "=r"(lo) : "f"(r));
}
__device__ __forceinline__ void mma8(float& c0, float& c1, float& c2, float& c3,
                                     uint32_t a0, uint32_t a1, uint32_t a2, uint32_t a3,
                                     uint32_t b0, uint32_t b1) {
    asm volatile(
        "mma.sync.aligned.m16n8k8.row.col.f32.tf32.tf32.f32 "
        "{%0,%1,%2,%3}, {%4,%5,%6,%7}, {%8,%9}, {%0,%1,%2,%3};"
        : "+f"(c0), "+f"(c1), "+f"(c2), "+f"(c3)
        : "r"(a0), "r"(a1), "r"(a2), "r"(a3), "r"(b0), "r"(b1));
}

// ============ Kernel 0: split X into (hi, lo) tf32 pairs ============
__global__ void k_prep(const float* __restrict__ X) {
    int i = blockIdx.x * blockDim.x + threadIdx.x;   // < 640000
    float x = X[i];
    uint32_t hi, lo;
    cvt3(x, hi, lo);
    g_X2[i] = make_uint2(hi, lo);
}

// ====== Kernel 1: H = A@X (3xTF32; 8 warps = 2 Mhalf x 4 Kslice) ======
__global__ __launch_bounds__(256, 3)
void k_gemm1(const float* __restrict__ A, const float* __restrict__ W) {
    extern __shared__ __align__(128) char sm[];
    const uint32_t smb = smem_u32(sm);
    const int tid  = threadIdx.x;
    const int wid  = tid >> 5;
    const int mh   = wid >> 2;        // 0/1: rows [mh*32, mh*32+32)
    const int ks   = wid & 3;         // k-slice: cols [8*ks, 8*ks+8)
    const int lane = tid & 31;
    const int g    = lane >> 2;       // 0..7
    const int tq   = lane & 3;        // 0..3
    const size_t m0 = (size_t)blockIdx.x * MTILE;

    // W -> smem [32][32]
    float* Ws = (float*)(sm + W_OFF);
#pragma unroll
    for (int u = 0; u < 4; u++) Ws[tid + 256 * u] = W[tid + 256 * u];

    auto load_stage = [&](int s, int t) {
        const uint32_t sb = smb + s * STAGEB;
        const int k0 = t * KTILE;
        // A: 64 rows x 32 floats = 512 x 16B slots, 2 per thread
#pragma unroll
        for (int u = 0; u < 2; u++) {
            int slot = tid + 256 * u;
            int r  = slot >> 3;               // 0..63
            int c4 = slot & 7;
            bool ok = (m0 + r) < NN;
            cp16(sb + (uint32_t)(r * APADF + c4 * 4) * 4,
                 A + (m0 + r) * NN + k0 + c4 * 4, ok);
        }
        // X2: 32 rows x 32 uint2 = 512 x 16B slots, 2 per thread
#pragma unroll
        for (int u = 0; u < 2; u++) {
            int slot = tid + 256 * u;
            int r  = slot >> 4;               // 0..31
            int c2 = slot & 15;
            cp16(sb + A_BYTES + (uint32_t)(r * XPAD2 + c2 * 2) * 8,
                 g_X2 + (size_t)(k0 + r) * KO + c2 * 2, true);
        }
        CP_COMMIT();
    };

    load_stage(0, 0);
    load_stage(1, 1);
    load_stage(2, 2);

    // acc[mt][nt][v]: 32 rows (this warp's m-half) x 32 cols, partial over k-slice
    float acc[2][4][4];
#pragma unroll
    for (int mt = 0; mt < 2; mt++)
#pragma unroll
        for (int nt = 0; nt < 4; nt++)
#pragma unroll
            for (int v = 0; v < 4; v++) acc[mt][nt][v] = 0.f;

    const int ksc = ks * 8;
    const int rbase = mh * 32;

    for (int t = 0; t < NTILES; t++) {
        const int s = t % NSTAGE;
        CP_WAIT2();
        __syncthreads();
        const float* As = (const float*)(sm + s * STAGEB);
        const uint2* Xs = (const uint2*)(sm + s * STAGEB + A_BYTES);

        // X fragments: this k-slice, pre-split
        const int kr = ksc + tq;
        uint2 xv0[4], xv1[4];
#pragma unroll
        for (int nt = 0; nt < 4; nt++) {
            int nc = nt * 8 + g;
            xv0[nt] = Xs[kr * XPAD2 + nc];
            xv1[nt] = Xs[(kr + 4) * XPAD2 + nc];
        }
        // A fragments: rows rbase + mt*16 + {g, g+8}, cols ksc + {tq, tq+4}
        uint32_t ahi[2][4], alo[2][4];
        const int c0 = ksc + tq;
#pragma unroll
        for (int mt = 0; mt < 2; mt++) {
            int r0 = rbase + mt * 16 + g;
            cvt3(As[r0 * APADF + c0],           ahi[mt][0], alo[mt][0]);
            cvt3(As[(r0 + 8) * APADF + c0],     ahi[mt][1], alo[mt][1]);
            cvt3(As[r0 * APADF + c0 + 4],       ahi[mt][2], alo[mt][2]);
            cvt3(As[(r0 + 8) * APADF + c0 + 4], ahi[mt][3], alo[mt][3]);
        }
#pragma unroll
        for (int mt = 0; mt < 2; mt++)
#pragma unroll
            for (int nt = 0; nt < 4; nt++) {
                mma8(acc[mt][nt][0], acc[mt][nt][1], acc[mt][nt][2], acc[mt][nt][3],
                     ahi[mt][0], ahi[mt][1], ahi[mt][2], ahi[mt][3],
                     xv0[nt].x, xv1[nt].x);
                mma8(acc[mt][nt][0], acc[mt][nt][1], acc[mt][nt][2], acc[mt][nt][3],
                     ahi[mt][0], ahi[mt][1], ahi[mt][2], ahi[mt][3],
                     xv0[nt].y, xv1[nt].y);
                mma8(acc[mt][nt][0], acc[mt][nt][1], acc[mt][nt][2], acc[mt][nt][3],
                     alo[mt][0], alo[mt][1], alo[mt][2], alo[mt][3],
                     xv0[nt].x, xv1[nt].x);
            }
        __syncthreads();
        if (t + NSTAGE < NTILES) load_stage(s, t + NSTAGE);
        else CP_COMMIT();   // keep group count aligned
    }
    CP_WAIT0();

    // ---- epilogue: K-partials -> smem Hp[4][64][33] (ks-major), fixed-order sum ----
    __syncthreads();
    float* Hp = (float*)sm;                       // 4*64*33*4 = 33792 B <= 55296
#pragma unroll
    for (int mt = 0; mt < 2; mt++) {
        int r0 = rbase + mt * 16 + g;
#pragma unroll
        for (int nt = 0; nt < 4; nt++) {
            int cc = nt * 8 + 2 * tq;
            float* Hw = Hp + ks * 64 * 33;
            Hw[r0 * 33 + cc]           = acc[mt][nt][0];
            Hw[r0 * 33 + cc + 1]       = acc[mt][nt][1];
            Hw[(r0 + 8) * 33 + cc]     = acc[mt][nt][2];
            Hw[(r0 + 8) * 33 + cc + 1] = acc[mt][nt][3];
        }
    }
    __syncthreads();

    float h2[32];
    if (tid < MTILE) {
        float h[32];
#pragma unroll
        for (int k = 0; k < 32; k++) {
            float v = Hp[tid * 33 + k];                    // deterministic: ks 0..3
            v += Hp[1 * 64 * 33 + tid * 33 + k];
            v += Hp[2 * 64 * 33 + tid * 33 + k];
            v += Hp[3 * 64 * 33 + tid * 33 + k];
            h[k] = v;
        }
#pragma unroll
        for (int n = 0; n < 32; n++) {
            float s = 0.f;
#pragma unroll
            for (int k = 0; k < 32; k++) s += h[k] * Ws[k * 32 + n];
            h2[n] = s;
        }
        size_t i = m0 + tid;
        if (i < NN) {
            float4* o = (float4*)(g_H2 + i * KO);
#pragma unroll
            for (int n4 = 0; n4 < 8; n4++)
                o[n4] = make_float4(h2[n4*4], h2[n4*4+1], h2[n4*4+2], h2[n4*4+3]);
        } else {
#pragma unroll
            for (int n = 0; n < 32; n++) h2[n] = 0.f;
        }
    }

    // deterministic fixed-order per-CTA BN partial reduction over 64 rows
    __syncthreads();
    float* red = (float*)sm;              // [64][32]
    float* rsq = (float*)(sm + 8192);     // [64][32]
    if (tid < MTILE) {
#pragma unroll
        for (int n = 0; n < 32; n++) {
            red[tid * 32 + n] = h2[n];
            rsq[tid * 32 + n] = h2[n] * h2[n];
        }
    }
    __syncthreads();
    for (int st = 32; st > 0; st >>= 1) {
        if (tid < st) {
#pragma unroll
            for (int n = 0; n < 32; n++) {
                red[tid * 32 + n] += red[(tid + st) * 32 + n];
                rsq[tid * 32 + n] += rsq[(tid + st) * 32 + n];
            }
        }
        __syncthreads();
    }
    if (tid < 32) {
        g_part[blockIdx.x * KO + tid] = red[tid];
        g_psq [blockIdx.x * KO + tid] = rsq[tid];
    }
}

// ================= Kernel 2: finalize BN stats (double) =================
__global__ void k_stats(const float* __restrict__ gamma,
                        const float* __restrict__ beta,
                        const float* __restrict__ bias) {
    int c = threadIdx.x;
    double s = 0.0, qq = 0.0;
    for (int b = 0; b < GRID1; b++) {
        s  += (double)g_part[b * KO + c];
        qq += (double)g_psq [b * KO + c];
    }
    double mean = s / (double)NN;
    double var  = qq / (double)NN - mean * mean;
    double inv  = 1.0 / sqrt(var + 1e-5);
    double gsc  = (double)gamma[c] * inv;
    g_scale[c] = (float)gsc;
    g_shift[c] = (float)((double)beta[c] + (double)bias[c] - mean * gsc);
}

// ================= Kernel 3: out = relu(H2*scale + shift) =================
__global__ void k_apply(float* __restrict__ out) {
    int idx4 = blockIdx.x * blockDim.x + threadIdx.x;
    float4 h  = *(const float4*)(g_H2 + (size_t)idx4 * 4);
    int cb    = (idx4 * 4) & 31;
    float4 sc = *(const float4*)(g_scale + cb);
    float4 sh = *(const float4*)(g_shift + cb);
    float4 o;
    o.x = fmaxf(h.x * sc.x + sh.x, 0.f);
    o.y = fmaxf(h.y * sc.y + sh.y, 0.f);
    o.z = fmaxf(h.z * sc.z + sh.z, 0.f);
    o.w = fmaxf(h.w * sc.w + sh.w, 0.f);
    *(float4*)(out + (size_t)idx4 * 4) = o;
}

// ================= launch =================
extern "C" void kernel_launch(void* const* d_in, const int* in_sizes, int n_in,
                              void* d_out, int out_size) {
    const float* A     = (const float*)d_in[0];
    const float* X     = (const float*)d_in[1];
    const float* W     = (const float*)d_in[2];
    const float* gamma = (const float*)d_in[3];
    const float* beta  = (const float*)d_in[4];
    const float* bias  = (const float*)d_in[5];
    float* out = (float*)d_out;

    cudaFuncSetAttribute(k_gemm1, cudaFuncAttributeMaxDynamicSharedMemorySize, SMEM_TOTAL);

    k_prep<<<(NN * KO) / 256, 256>>>(X);
    k_gemm1<<<GRID1, 256, SMEM_TOTAL>>>(A, W);
    k_stats<<<1, KO>>>(gamma, beta, bias);
    k_apply<<<(NN * KO / 4) / 256, 256>>>(out);
}

// round 9
// speedup vs baseline: 1.5933x; 1.5933x over previous
#include <cuda_runtime.h>
#include <cstdint>

#define NN     20000
#define KO     32
#define MTILE  48
#define KTILE  32
#define NTILES 625          // 20000/32 exact
#define GRID1  417          // ceil(20000/48) -> covers 20016, pad rows zeroed

#define APADF  36                     // A smem row stride (floats)
#define XPADF  40                     // X smem row stride (floats)
#define A_BYTES (MTILE * APADF * 4)   // 6912
#define X_BYTES (KTILE * XPADF * 4)   // 5120
#define STAGEB  (A_BYTES + X_BYTES)   // 12032
#define NSTAGE  3
#define W_OFF   (STAGEB * NSTAGE)     // 36096
#define SMEM_TOTAL (W_OFF + 4096)     // 40192

#define TFMASK 0xFFFFE000u

// ---- scratch (no allocations allowed) ----
__device__ __align__(16) float g_H2 [NN * KO];
__device__ __align__(16) float g_part[GRID1 * KO];
__device__ __align__(16) float g_psq [GRID1 * KO];
__device__ float g_scale[KO];
__device__ float g_shift[KO];

// ================= helpers =================
__device__ __forceinline__ uint32_t smem_u32(const void* p) {
    uint32_t a;
    asm("{ .reg .u64 t; cvta.to.shared.u64 t, %1; cvt.u32.u64 %0, t; }" : "=r"(a) : "l"(p));
    return a;
}
__device__ __forceinline__ void cp16(uint32_t dst, const void* src, bool ok) {
    asm volatile("cp.async.cg.shared.global [%0], [%1], 16, %2;"
                 :: "r"(dst), "l"(src), "r"(ok ? 16u : 0u) : "memory");
}
#define CP_COMMIT() asm volatile("cp.async.commit_group;" ::: "memory")
#define CP_WAIT2()  asm volatile("cp.async.wait_group 2;" ::: "memory")
#define CP_WAIT0()  asm volatile("cp.async.wait_group 0;" ::: "memory")

// RZ split: hi = a masked to tf32 (exact), lo = a - hi (fed raw; HW truncates, err ~2^-21)
__device__ __forceinline__ void msplit(float a, uint32_t& hi, uint32_t& lo) {
    uint32_t hm = __float_as_uint(a) & TFMASK;   // LOP3 (alu)
    hi = hm;
    lo = __float_as_uint(a - __uint_as_float(hm));  // FADD (fma pipe)
}
__device__ __forceinline__ void mma8(float& c0, float& c1, float& c2, float& c3,
                                     uint32_t a0, uint32_t a1, uint32_t a2, uint32_t a3,
                                     uint32_t b0, uint32_t b1) {
    asm volatile(
        "mma.sync.aligned.m16n8k8.row.col.f32.tf32.tf32.f32 "
        "{%0,%1,%2,%3}, {%4,%5,%6,%7}, {%8,%9}, {%0,%1,%2,%3};"
        : "+f"(c0), "+f"(c1), "+f"(c2), "+f"(c3)
        : "r"(a0), "r"(a1), "r"(a2), "r"(a3), "r"(b0), "r"(b1));
}

// ====== Kernel 1: H = A@X (3xTF32, K-split warps, RZ mask-split) ======
__global__ __launch_bounds__(128, 3)
void k_gemm1(const float* __restrict__ A, const float* __restrict__ X,
             const float* __restrict__ W) {
    extern __shared__ __align__(128) char sm[];
    const uint32_t smb = smem_u32(sm);
    const int tid  = threadIdx.x;
    const int wid  = tid >> 5;        // warp owns k-cols [8*wid, 8*wid+8)
    const int lane = tid & 31;
    const int g    = lane >> 2;       // 0..7
    const int tq   = lane & 3;        // 0..3
    const size_t m0 = (size_t)blockIdx.x * MTILE;

    // W -> smem [32][32]
    float* Ws = (float*)(sm + W_OFF);
#pragma unroll
    for (int u = 0; u < 8; u++) Ws[tid + 128 * u] = W[tid + 128 * u];

    auto load_stage = [&](int s, int t) {
        const uint32_t sb = smb + s * STAGEB;
        const int k0 = t * KTILE;
        // A: 48 rows x 32 floats = 384 x 16B slots, 3 per thread
#pragma unroll
        for (int u = 0; u < 3; u++) {
            int slot = tid + 128 * u;
            int r  = slot >> 3;               // 0..47
            int c4 = slot & 7;
            bool ok = (m0 + r) < NN;
            cp16(sb + (uint32_t)(r * APADF + c4 * 4) * 4,
                 A + (m0 + r) * NN + k0 + c4 * 4, ok);
        }
        // X: 32 rows x 32 floats = 256 x 16B slots, 2 per thread
#pragma unroll
        for (int u = 0; u < 2; u++) {
            int slot = tid + 128 * u;
            int r  = slot >> 3;               // 0..31
            int c4 = slot & 7;
            cp16(sb + A_BYTES + (uint32_t)(r * XPADF + c4 * 4) * 4,
                 X + (size_t)(k0 + r) * KO + c4 * 4, true);
        }
        CP_COMMIT();
    };

    load_stage(0, 0);
    load_stage(1, 1);
    load_stage(2, 2);

    // acc[mt][nt][v]: 48 rows x 32 cols, partial over this warp's k-slice
    float acc[3][4][4];
#pragma unroll
    for (int mt = 0; mt < 3; mt++)
#pragma unroll
        for (int nt = 0; nt < 4; nt++)
#pragma unroll
            for (int v = 0; v < 4; v++) acc[mt][nt][v] = 0.f;

    const int ksc = wid * 8;

    for (int t = 0; t < NTILES; t++) {
        const int s = t % NSTAGE;
        CP_WAIT2();
        __syncthreads();
        const float* As = (const float*)(sm + s * STAGEB);
        const float* Xs = (const float*)(sm + s * STAGEB + A_BYTES);

        // X fragments for this warp's k-slice
        uint32_t bhi[4][2], blo[4][2];
        const int kr = ksc + tq;
#pragma unroll
        for (int nt = 0; nt < 4; nt++) {
            int nc = nt * 8 + g;
            msplit(Xs[kr * XPADF + nc],       bhi[nt][0], blo[nt][0]);
            msplit(Xs[(kr + 4) * XPADF + nc], bhi[nt][1], blo[nt][1]);
        }
        // A fragments: 3 m-tiles x 4 values
        uint32_t ahi[3][4], alo[3][4];
        const int c0 = ksc + tq;
#pragma unroll
        for (int mt = 0; mt < 3; mt++) {
            int r0 = mt * 16 + g;
            msplit(As[r0 * APADF + c0],           ahi[mt][0], alo[mt][0]);
            msplit(As[(r0 + 8) * APADF + c0],     ahi[mt][1], alo[mt][1]);
            msplit(As[r0 * APADF + c0 + 4],       ahi[mt][2], alo[mt][2]);
            msplit(As[(r0 + 8) * APADF + c0 + 4], ahi[mt][3], alo[mt][3]);
        }
#pragma unroll
        for (int mt = 0; mt < 3; mt++)
#pragma unroll
            for (int nt = 0; nt < 4; nt++) {
                mma8(acc[mt][nt][0], acc[mt][nt][1], acc[mt][nt][2], acc[mt][nt][3],
                     ahi[mt][0], ahi[mt][1], ahi[mt][2], ahi[mt][3],
                     bhi[nt][0], bhi[nt][1]);
                mma8(acc[mt][nt][0], acc[mt][nt][1], acc[mt][nt][2], acc[mt][nt][3],
                     ahi[mt][0], ahi[mt][1], ahi[mt][2], ahi[mt][3],
                     blo[nt][0], blo[nt][1]);
                mma8(acc[mt][nt][0], acc[mt][nt][1], acc[mt][nt][2], acc[mt][nt][3],
                     alo[mt][0], alo[mt][1], alo[mt][2], alo[mt][3],
                     bhi[nt][0], bhi[nt][1]);
            }
        __syncthreads();
        if (t + NSTAGE < NTILES) load_stage(s, t + NSTAGE);
        else CP_COMMIT();   // keep group count aligned
    }
    CP_WAIT0();

    // ---- epilogue: per-warp K-partials -> smem Hp[4][48][33], fixed-order sum ----
    __syncthreads();
    float* Hp = (float*)sm;                       // 4*48*33*4 = 25344 B
#pragma unroll
    for (int mt = 0; mt < 3; mt++) {
        int r0 = mt * 16 + g;
#pragma unroll
        for (int nt = 0; nt < 4; nt++) {
            int cc = nt * 8 + 2 * tq;
            float* Hw = Hp + wid * MTILE * 33;
            Hw[r0 * 33 + cc]           = acc[mt][nt][0];
            Hw[r0 * 33 + cc + 1]       = acc[mt][nt][1];
            Hw[(r0 + 8) * 33 + cc]     = acc[mt][nt][2];
            Hw[(r0 + 8) * 33 + cc + 1] = acc[mt][nt][3];
        }
    }
    __syncthreads();

    float h2[32];
    if (tid < MTILE) {
        float h[32];
#pragma unroll
        for (int k = 0; k < 32; k++) {
            float v = Hp[tid * 33 + k];                    // deterministic: warp 0..3
            v += Hp[1 * MTILE * 33 + tid * 33 + k];
            v += Hp[2 * MTILE * 33 + tid * 33 + k];
            v += Hp[3 * MTILE * 33 + tid * 33 + k];
            h[k] = v;
        }
#pragma unroll
        for (int n = 0; n < 32; n++) {
            float s = 0.f;
#pragma unroll
            for (int k = 0; k < 32; k++) s += h[k] * Ws[k * 32 + n];
            h2[n] = s;
        }
        size_t i = m0 + tid;
        if (i < NN) {
            float4* o = (float4*)(g_H2 + i * KO);
#pragma unroll
            for (int n4 = 0; n4 < 8; n4++)
                o[n4] = make_float4(h2[n4*4], h2[n4*4+1], h2[n4*4+2], h2[n4*4+3]);
        } else {
#pragma unroll
            for (int n = 0; n < 32; n++) h2[n] = 0.f;
        }
    }

    // deterministic fixed-order per-CTA BN partial reduction over 48 rows
    __syncthreads();
    float* red = (float*)sm;              // [48][32]
    float* rsq = (float*)(sm + 8192);     // [48][32]
    if (tid < MTILE) {
#pragma unroll
        for (int n = 0; n < 32; n++) {
            red[tid * 32 + n] = h2[n];
            rsq[tid * 32 + n] = h2[n] * h2[n];
        }
    }
    __syncthreads();
    if (tid < 16) {
#pragma unroll
        for (int n = 0; n < 32; n++) {
            red[tid * 32 + n] = red[tid * 32 + n] + red[(tid + 16) * 32 + n]
                              + red[(tid + 32) * 32 + n];
            rsq[tid * 32 + n] = rsq[tid * 32 + n] + rsq[(tid + 16) * 32 + n]
                              + rsq[(tid + 32) * 32 + n];
        }
    }
    __syncthreads();
    for (int st = 8; st > 0; st >>= 1) {
        if (tid < st) {
#pragma unroll
            for (int n = 0; n < 32; n++) {
                red[tid * 32 + n] += red[(tid + st) * 32 + n];
                rsq[tid * 32 + n] += rsq[(tid + st) * 32 + n];
            }
        }
        __syncthreads();
    }
    if (tid < 32) {
        g_part[blockIdx.x * KO + tid] = red[tid];
        g_psq [blockIdx.x * KO + tid] = rsq[tid];
    }
}

// ================= Kernel 2: finalize BN stats (double) =================
__global__ void k_stats(const float* __restrict__ gamma,
                        const float* __restrict__ beta,
                        const float* __restrict__ bias) {
    int c = threadIdx.x;
    double s = 0.0, qq = 0.0;
    for (int b = 0; b < GRID1; b++) {
        s  += (double)g_part[b * KO + c];
        qq += (double)g_psq [b * KO + c];
    }
    double mean = s / (double)NN;
    double var  = qq / (double)NN - mean * mean;
    double inv  = 1.0 / sqrt(var + 1e-5);
    double gsc  = (double)gamma[c] * inv;
    g_scale[c] = (float)gsc;
    g_shift[c] = (float)((double)beta[c] + (double)bias[c] - mean * gsc);
}

// ================= Kernel 3: out = relu(H2*scale + shift) =================
__global__ void k_apply(float* __restrict__ out) {
    int idx4 = blockIdx.x * blockDim.x + threadIdx.x;
    float4 h  = *(const float4*)(g_H2 + (size_t)idx4 * 4);
    int cb    = (idx4 * 4) & 31;
    float4 sc = *(const float4*)(g_scale + cb);
    float4 sh = *(const float4*)(g_shift + cb);
    float4 o;
    o.x = fmaxf(h.x * sc.x + sh.x, 0.f);
    o.y = fmaxf(h.y * sc.y + sh.y, 0.f);
    o.z = fmaxf(h.z * sc.z + sh.z, 0.f);
    o.w = fmaxf(h.w * sc.w + sh.w, 0.f);
    *(float4*)(out + (size_t)idx4 * 4) = o;
}

// ================= launch =================
extern "C" void kernel_launch(void* const* d_in, const int* in_sizes, int n_in,
                              void* d_out, int out_size) {
    const float* A     = (const float*)d_in[0];
    const float* X     = (const float*)d_in[1];
    const float* W     = (const float*)d_in[2];
    const float* gamma = (const float*)d_in[3];
    const float* beta  = (const float*)d_in[4];
    const float* bias  = (const float*)d_in[5];
    float* out = (float*)d_out;

    cudaFuncSetAttribute(k_gemm1, cudaFuncAttributeMaxDynamicSharedMemorySize, SMEM_TOTAL);

    k_gemm1<<<GRID1, 128, SMEM_TOTAL>>>(A, X, W);
    k_stats<<<1, KO>>>(gamma, beta, bias);
    k_apply<<<(NN * KO / 4) / 256, 256>>>(out);
}

// round 10
// speedup vs baseline: 2.0484x; 1.2857x over previous
#include <cuda_runtime.h>
#include <cstdint>

#define NN     20000
#define KO     32
#define MTILE  48
#define KTILE  32
#define NTILES 625          // 20000/32
#define TSPLIT 313          // khalf 0: [0,313), khalf 1: [313,625)
#define GRIDM  417          // ceil(20000/48)
#define SBLK   157          // combine blocks

#define APADF  36                     // A smem row stride (floats): 4g+tq banks, conflict-free
#define XPADF  40                     // X smem row stride (floats): 8tq+g banks, conflict-free
#define A_BYTES (MTILE * APADF * 4)   // 6912
#define X_BYTES (KTILE * XPADF * 4)   // 5120
#define STAGEB  (A_BYTES + X_BYTES)   // 12032
#define NSTAGE  3
#define SMEM_TOTAL (STAGEB * NSTAGE)  // 36096 -> 5 CTAs/SM

#define TFMASK 0xFFFFE000u

// ---- scratch (no allocations allowed) ----
__device__ __align__(16) float g_Hp [2 * NN * KO];   // K-split partial H planes
__device__ __align__(16) float g_H2 [NN * KO];
__device__ __align__(16) float g_part[SBLK * KO];
__device__ __align__(16) float g_psq [SBLK * KO];
__device__ float g_scale[KO];
__device__ float g_shift[KO];

// ================= helpers =================
__device__ __forceinline__ uint32_t smem_u32(const void* p) {
    uint32_t a;
    asm("{ .reg .u64 t; cvta.to.shared.u64 t, %1; cvt.u32.u64 %0, t; }" : "=r"(a) : "l"(p));
    return a;
}
__device__ __forceinline__ void cp16(uint32_t dst, const void* src, bool ok) {
    asm volatile("cp.async.cg.shared.global [%0], [%1], 16, %2;"
                 :: "r"(dst), "l"(src), "r"(ok ? 16u : 0u) : "memory");
}
#define CP_COMMIT() asm volatile("cp.async.commit_group;" ::: "memory")
#define CP_WAIT2()  asm volatile("cp.async.wait_group 2;" ::: "memory")
#define CP_WAIT0()  asm volatile("cp.async.wait_group 0;" ::: "memory")

// A split: hi = masked tf32 (exact RZ), lo = a - hi (fed raw, HW truncates)
__device__ __forceinline__ void msplit(float a, uint32_t& hi, uint32_t& lo) {
    uint32_t hm = __float_as_uint(a) & TFMASK;
    hi = hm;
    lo = __float_as_uint(a - __uint_as_float(hm));
}
__device__ __forceinline__ void mma8(float& c0, float& c1, float& c2, float& c3,
                                     uint32_t a0, uint32_t a1, uint32_t a2, uint32_t a3,
                                     uint32_t b0, uint32_t b1) {
    asm volatile(
        "mma.sync.aligned.m16n8k8.row.col.f32.tf32.tf32.f32 "
        "{%0,%1,%2,%3}, {%4,%5,%6,%7}, {%8,%9}, {%0,%1,%2,%3};"
        : "+f"(c0), "+f"(c1), "+f"(c2), "+f"(c3)
        : "r"(a0), "r"(a1), "r"(a2), "r"(a3), "r"(b0), "r"(b1));
}

// ====== Kernel 1: partial H = A[:, jrange] @ X[jrange] (2xTF32, K-split warps+CTAs) ======
__global__ __launch_bounds__(128, 5)
void k_gemm1(const float* __restrict__ A, const float* __restrict__ X) {
    extern __shared__ __align__(128) char sm[];
    const uint32_t smb = smem_u32(sm);
    const int tid  = threadIdx.x;
    const int wid  = tid >> 5;        // warp owns k-cols [8*wid, 8*wid+8) of each tile
    const int lane = tid & 31;
    const int g    = lane >> 2;       // 0..7
    const int tq   = lane & 3;        // 0..3
    const size_t m0 = (size_t)blockIdx.x * MTILE;
    const int khalf = blockIdx.y;
    const int T0 = khalf ? TSPLIT : 0;
    const int T1 = khalf ? NTILES : TSPLIT;

    auto load_stage = [&](int s, int t) {
        const uint32_t sb = smb + s * STAGEB;
        const int k0 = t * KTILE;
        // A: 48 rows x 32 floats = 384 x 16B slots, 3 per thread
#pragma unroll
        for (int u = 0; u < 3; u++) {
            int slot = tid + 128 * u;
            int r  = slot >> 3;
            int c4 = slot & 7;
            bool ok = (m0 + r) < NN;
            cp16(sb + (uint32_t)(r * APADF + c4 * 4) * 4,
                 A + (m0 + r) * NN + k0 + c4 * 4, ok);
        }
        // X: 32 rows x 32 floats = 256 x 16B slots, 2 per thread
#pragma unroll
        for (int u = 0; u < 2; u++) {
            int slot = tid + 128 * u;
            int r  = slot >> 3;
            int c4 = slot & 7;
            cp16(sb + A_BYTES + (uint32_t)(r * XPADF + c4 * 4) * 4,
                 X + (size_t)(k0 + r) * KO + c4 * 4, true);
        }
        CP_COMMIT();
    };

    load_stage(0, T0);
    load_stage(1, T0 + 1);
    load_stage(2, T0 + 2);

    float acc[3][4][4];
#pragma unroll
    for (int mt = 0; mt < 3; mt++)
#pragma unroll
        for (int nt = 0; nt < 4; nt++)
#pragma unroll
            for (int v = 0; v < 4; v++) acc[mt][nt][v] = 0.f;

    const int ksc = wid * 8;

    for (int t = T0; t < T1; t++) {
        const int s = (t - T0) % NSTAGE;
        CP_WAIT2();
        __syncthreads();
        const float* As = (const float*)(sm + s * STAGEB);
        const float* Xs = (const float*)(sm + s * STAGEB + A_BYTES);

        // X fragments: hi-only (masked), this warp's k-slice
        uint32_t bhi[4][2];
        const int kr = ksc + tq;
#pragma unroll
        for (int nt = 0; nt < 4; nt++) {
            int nc = nt * 8 + g;
            bhi[nt][0] = __float_as_uint(Xs[kr * XPADF + nc])       & TFMASK;
            bhi[nt][1] = __float_as_uint(Xs[(kr + 4) * XPADF + nc]) & TFMASK;
        }
        // A fragments: hi+lo split
        uint32_t ahi[3][4], alo[3][4];
        const int c0 = ksc + tq;
#pragma unroll
        for (int mt = 0; mt < 3; mt++) {
            int r0 = mt * 16 + g;
            msplit(As[r0 * APADF + c0],           ahi[mt][0], alo[mt][0]);
            msplit(As[(r0 + 8) * APADF + c0],     ahi[mt][1], alo[mt][1]);
            msplit(As[r0 * APADF + c0 + 4],       ahi[mt][2], alo[mt][2]);
            msplit(As[(r0 + 8) * APADF + c0 + 4], ahi[mt][3], alo[mt][3]);
        }
#pragma unroll
        for (int mt = 0; mt < 3; mt++)
#pragma unroll
            for (int nt = 0; nt < 4; nt++) {
                mma8(acc[mt][nt][0], acc[mt][nt][1], acc[mt][nt][2], acc[mt][nt][3],
                     ahi[mt][0], ahi[mt][1], ahi[mt][2], ahi[mt][3],
                     bhi[nt][0], bhi[nt][1]);
                mma8(acc[mt][nt][0], acc[mt][nt][1], acc[mt][nt][2], acc[mt][nt][3],
                     alo[mt][0], alo[mt][1], alo[mt][2], alo[mt][3],
                     bhi[nt][0], bhi[nt][1]);
            }
        __syncthreads();
        if (t + NSTAGE < T1) load_stage(s, t + NSTAGE);
        else CP_COMMIT();   // keep group count aligned
    }
    CP_WAIT0();

    // ---- epilogue: 4 warp K-partials -> smem -> fixed-order sum -> g_Hp plane ----
    __syncthreads();
    float* Hp = (float*)sm;                       // 4*48*33*4 = 25344 B <= 36096
#pragma unroll
    for (int mt = 0; mt < 3; mt++) {
        int r0 = mt * 16 + g;
#pragma unroll
        for (int nt = 0; nt < 4; nt++) {
            int cc = nt * 8 + 2 * tq;
            float* Hw = Hp + wid * MTILE * 33;
            Hw[r0 * 33 + cc]           = acc[mt][nt][0];
            Hw[r0 * 33 + cc + 1]       = acc[mt][nt][1];
            Hw[(r0 + 8) * 33 + cc]     = acc[mt][nt][2];
            Hw[(r0 + 8) * 33 + cc + 1] = acc[mt][nt][3];
        }
    }
    __syncthreads();

    if (tid < MTILE && (m0 + tid) < NN) {
        float h[32];
#pragma unroll
        for (int k = 0; k < 32; k++) {
            float v = Hp[tid * 33 + k];                    // deterministic: warp 0..3
            v += Hp[1 * MTILE * 33 + tid * 33 + k];
            v += Hp[2 * MTILE * 33 + tid * 33 + k];
            v += Hp[3 * MTILE * 33 + tid * 33 + k];
            h[k] = v;
        }
        float4* o = (float4*)(g_Hp + ((size_t)khalf * NN + m0 + tid) * KO);
#pragma unroll
        for (int n4 = 0; n4 < 8; n4++)
            o[n4] = make_float4(h[n4*4], h[n4*4+1], h[n4*4+2], h[n4*4+3]);
    }
}

// ====== Kernel 2: combine K-halves, h2 = h @ W, BN partials (deterministic) ======
__global__ __launch_bounds__(128)
void k_combine(const float* __restrict__ W) {
    __shared__ float Ws[32 * 32];
    __shared__ float red[128 * 32];
    const int tid = threadIdx.x;
#pragma unroll
    for (int u = 0; u < 8; u++) Ws[tid + 128 * u] = W[tid + 128 * u];
    __syncthreads();

    const size_t row = (size_t)blockIdx.x * 128 + tid;
    float h2[32];
    bool valid = row < NN;
    if (valid) {
        const float4* p0 = (const float4*)(g_Hp + row * KO);
        const float4* p1 = (const float4*)(g_Hp + ((size_t)NN + row) * KO);
        float h[32];
#pragma unroll
        for (int q = 0; q < 8; q++) {
            float4 a = p0[q], b = p1[q];
            h[q*4+0] = a.x + b.x; h[q*4+1] = a.y + b.y;
            h[q*4+2] = a.z + b.z; h[q*4+3] = a.w + b.w;
        }
#pragma unroll
        for (int n = 0; n < 32; n++) {
            float s = 0.f;
#pragma unroll
            for (int k = 0; k < 32; k++) s += h[k] * Ws[k * 32 + n];
            h2[n] = s;
        }
        float4* o = (float4*)(g_H2 + row * KO);
#pragma unroll
        for (int q = 0; q < 8; q++)
            o[q] = make_float4(h2[q*4], h2[q*4+1], h2[q*4+2], h2[q*4+3]);
    } else {
#pragma unroll
        for (int n = 0; n < 32; n++) h2[n] = 0.f;
    }

    // fixed-order block reduction: sums
#pragma unroll
    for (int n = 0; n < 32; n++) red[tid * 32 + n] = h2[n];
    __syncthreads();
    for (int st = 64; st > 0; st >>= 1) {
        if (tid < st) {
#pragma unroll
            for (int n = 0; n < 32; n++)
                red[tid * 32 + n] += red[(tid + st) * 32 + n];
        }
        __syncthreads();
    }
    if (tid < 32) g_part[blockIdx.x * KO + tid] = red[tid];
    __syncthreads();
    // squares
#pragma unroll
    for (int n = 0; n < 32; n++) red[tid * 32 + n] = h2[n] * h2[n];
    __syncthreads();
    for (int st = 64; st > 0; st >>= 1) {
        if (tid < st) {
#pragma unroll
            for (int n = 0; n < 32; n++)
                red[tid * 32 + n] += red[(tid + st) * 32 + n];
        }
        __syncthreads();
    }
    if (tid < 32) g_psq[blockIdx.x * KO + tid] = red[tid];
}

// ================= Kernel 3: finalize BN stats (double) =================
__global__ void k_stats(const float* __restrict__ gamma,
                        const float* __restrict__ beta,
                        const float* __restrict__ bias) {
    int c = threadIdx.x;
    double s = 0.0, qq = 0.0;
    for (int b = 0; b < SBLK; b++) {
        s  += (double)g_part[b * KO + c];
        qq += (double)g_psq [b * KO + c];
    }
    double mean = s / (double)NN;
    double var  = qq / (double)NN - mean * mean;
    double inv  = 1.0 / sqrt(var + 1e-5);
    double gsc  = (double)gamma[c] * inv;
    g_scale[c] = (float)gsc;
    g_shift[c] = (float)((double)beta[c] + (double)bias[c] - mean * gsc);
}

// ================= Kernel 4: out = relu(H2*scale + shift) =================
__global__ void k_apply(float* __restrict__ out) {
    int idx4 = blockIdx.x * blockDim.x + threadIdx.x;
    float4 h  = *(const float4*)(g_H2 + (size_t)idx4 * 4);
    int cb    = (idx4 * 4) & 31;
    float4 sc = *(const float4*)(g_scale + cb);
    float4 sh = *(const float4*)(g_shift + cb);
    float4 o;
    o.x = fmaxf(h.x * sc.x + sh.x, 0.f);
    o.y = fmaxf(h.y * sc.y + sh.y, 0.f);
    o.z = fmaxf(h.z * sc.z + sh.z, 0.f);
    o.w = fmaxf(h.w * sc.w + sh.w, 0.f);
    *(float4*)(out + (size_t)idx4 * 4) = o;
}

// ================= launch =================
extern "C" void kernel_launch(void* const* d_in, const int* in_sizes, int n_in,
                              void* d_out, int out_size) {
    const float* A     = (const float*)d_in[0];
    const float* X     = (const float*)d_in[1];
    const float* W     = (const float*)d_in[2];
    const float* gamma = (const float*)d_in[3];
    const float* beta  = (const float*)d_in[4];
    const float* bias  = (const float*)d_in[5];
    float* out = (float*)d_out;

    cudaFuncSetAttribute(k_gemm1, cudaFuncAttributeMaxDynamicSharedMemorySize, SMEM_TOTAL);

    k_gemm1<<<dim3(GRIDM, 2), 128, SMEM_TOTAL>>>(A, X);
    k_combine<<<SBLK, 128>>>(W);
    k_stats<<<1, KO>>>(gamma, beta, bias);
    k_apply<<<(NN * KO / 4) / 256, 256>>>(out);
}

// round 11
// speedup vs baseline: 2.2058x; 1.0768x over previous
#include <cuda_runtime.h>
#include <cstdint>

#define NN     20000
#define KO     32
#define MTILE  48
#define KTILE  32
#define NTILES 625          // 20000/32
#define TSPLIT 313          // khalf 0: [0,313), khalf 1: [313,625)
#define GRIDM  417          // ceil(20000/48)
#define SBLK   157          // combine blocks

#define APADF  36                     // A smem row stride (floats)
#define XPADF  40                     // X smem row stride (floats)
#define A_BYTES (MTILE * APADF * 4)   // 6912
#define X_BYTES (KTILE * XPADF * 4)   // 5120
#define STAGEB  (A_BYTES + X_BYTES)   // 12032
#define NSTAGE  3
#define SMEM_TOTAL (STAGEB * NSTAGE)  // 36096 -> 5 CTAs/SM

#define TFMASK 0xFFFFE000u

// ---- scratch (no allocations allowed) ----
__device__ __align__(16) float g_Hp [2 * NN * KO];   // K-split partial H planes
__device__ __align__(16) float g_H2 [NN * KO];
__device__ __align__(16) float g_part[SBLK * KO];
__device__ __align__(16) float g_psq [SBLK * KO];
__device__ float g_scale[KO];
__device__ float g_shift[KO];

// ================= helpers =================
__device__ __forceinline__ uint32_t smem_u32(const void* p) {
    uint32_t a;
    asm("{ .reg .u64 t; cvta.to.shared.u64 t, %1; cvt.u32.u64 %0, t; }" : "=r"(a) : "l"(p));
    return a;
}
__device__ __forceinline__ void cp16(uint32_t dst, const void* src, bool ok) {
    asm volatile("cp.async.cg.shared.global [%0], [%1], 16, %2;"
                 :: "r"(dst), "l"(src), "r"(ok ? 16u : 0u) : "memory");
}
#define CP_COMMIT() asm volatile("cp.async.commit_group;" ::: "memory")
#define CP_WAIT2()  asm volatile("cp.async.wait_group 2;" ::: "memory")
#define CP_WAIT0()  asm volatile("cp.async.wait_group 0;" ::: "memory")

// A split: hi = masked tf32 (exact RZ), lo = a - hi (fed raw, HW truncates)
__device__ __forceinline__ void msplit(float a, uint32_t& hi, uint32_t& lo) {
    uint32_t hm = __float_as_uint(a) & TFMASK;
    hi = hm;
    lo = __float_as_uint(a - __uint_as_float(hm));
}
__device__ __forceinline__ void mma8(float& c0, float& c1, float& c2, float& c3,
                                     uint32_t a0, uint32_t a1, uint32_t a2, uint32_t a3,
                                     uint32_t b0, uint32_t b1) {
    asm volatile(
        "mma.sync.aligned.m16n8k8.row.col.f32.tf32.tf32.f32 "
        "{%0,%1,%2,%3}, {%4,%5,%6,%7}, {%8,%9}, {%0,%1,%2,%3};"
        : "+f"(c0), "+f"(c1), "+f"(c2), "+f"(c3)
        : "r"(a0), "r"(a1), "r"(a2), "r"(a3), "r"(b0), "r"(b1));
}

// ====== Kernel 1: partial H = A[:, jrange] @ X[jrange] (2xTF32, early-release pipeline) ======
__global__ __launch_bounds__(128, 5)
void k_gemm1(const float* __restrict__ A, const float* __restrict__ X) {
    extern __shared__ __align__(128) char sm[];
    const uint32_t smb = smem_u32(sm);
    const int tid  = threadIdx.x;
    const int wid  = tid >> 5;        // warp owns k-cols [8*wid, 8*wid+8) of each tile
    const int lane = tid & 31;
    const int g    = lane >> 2;       // 0..7
    const int tq   = lane & 3;        // 0..3
    const size_t m0 = (size_t)blockIdx.x * MTILE;
    const int khalf = blockIdx.y;
    const int T0 = khalf ? TSPLIT : 0;
    const int T1 = khalf ? NTILES : TSPLIT;

    auto load_stage = [&](int s, int t) {
        const uint32_t sb = smb + s * STAGEB;
        const int k0 = t * KTILE;
#pragma unroll
        for (int u = 0; u < 3; u++) {
            int slot = tid + 128 * u;
            int r  = slot >> 3;
            int c4 = slot & 7;
            bool ok = (m0 + r) < NN;
            cp16(sb + (uint32_t)(r * APADF + c4 * 4) * 4,
                 A + (m0 + r) * NN + k0 + c4 * 4, ok);
        }
#pragma unroll
        for (int u = 0; u < 2; u++) {
            int slot = tid + 128 * u;
            int r  = slot >> 3;
            int c4 = slot & 7;
            cp16(sb + A_BYTES + (uint32_t)(r * XPADF + c4 * 4) * 4,
                 X + (size_t)(k0 + r) * KO + c4 * 4, true);
        }
        CP_COMMIT();
    };

    load_stage(0, T0);
    load_stage(1, T0 + 1);
    load_stage(2, T0 + 2);

    float acc[3][4][4];
#pragma unroll
    for (int mt = 0; mt < 3; mt++)
#pragma unroll
        for (int nt = 0; nt < 4; nt++)
#pragma unroll
            for (int v = 0; v < 4; v++) acc[mt][nt][v] = 0.f;

    const int ksc = wid * 8;

    for (int t = T0; t < T1; t++) {
        const int s = (t - T0) % NSTAGE;
        CP_WAIT2();
        __syncthreads();
        const float* As = (const float*)(sm + s * STAGEB);
        const float* Xs = (const float*)(sm + s * STAGEB + A_BYTES);

        // ---- fragment phase: everything stage s -> registers ----
        uint32_t bhi[4][2];
        const int kr = ksc + tq;
#pragma unroll
        for (int nt = 0; nt < 4; nt++) {
            int nc = nt * 8 + g;
            bhi[nt][0] = __float_as_uint(Xs[kr * XPADF + nc])       & TFMASK;
            bhi[nt][1] = __float_as_uint(Xs[(kr + 4) * XPADF + nc]) & TFMASK;
        }
        uint32_t ahi[3][4], alo[3][4];
        const int c0 = ksc + tq;
#pragma unroll
        for (int mt = 0; mt < 3; mt++) {
            int r0 = mt * 16 + g;
            msplit(As[r0 * APADF + c0],           ahi[mt][0], alo[mt][0]);
            msplit(As[(r0 + 8) * APADF + c0],     ahi[mt][1], alo[mt][1]);
            msplit(As[r0 * APADF + c0 + 4],       ahi[mt][2], alo[mt][2]);
            msplit(As[(r0 + 8) * APADF + c0 + 4], ahi[mt][3], alo[mt][3]);
        }
        // ---- stage s released: issue next load BEFORE compute ----
        __syncthreads();
        if (t + NSTAGE < T1) load_stage(s, t + NSTAGE);
        else CP_COMMIT();   // keep group count aligned

        // ---- MMA phase overlaps fresh cp.async stream ----
#pragma unroll
        for (int mt = 0; mt < 3; mt++)
#pragma unroll
            for (int nt = 0; nt < 4; nt++) {
                mma8(acc[mt][nt][0], acc[mt][nt][1], acc[mt][nt][2], acc[mt][nt][3],
                     ahi[mt][0], ahi[mt][1], ahi[mt][2], ahi[mt][3],
                     bhi[nt][0], bhi[nt][1]);
                mma8(acc[mt][nt][0], acc[mt][nt][1], acc[mt][nt][2], acc[mt][nt][3],
                     alo[mt][0], alo[mt][1], alo[mt][2], alo[mt][3],
                     bhi[nt][0], bhi[nt][1]);
            }
    }
    CP_WAIT0();

    // ---- epilogue: 4 warp K-partials -> smem -> fixed-order sum -> g_Hp plane ----
    __syncthreads();
    float* Hp = (float*)sm;                       // 4*48*33*4 = 25344 B <= 36096
#pragma unroll
    for (int mt = 0; mt < 3; mt++) {
        int r0 = mt * 16 + g;
#pragma unroll
        for (int nt = 0; nt < 4; nt++) {
            int cc = nt * 8 + 2 * tq;
            float* Hw = Hp + wid * MTILE * 33;
            Hw[r0 * 33 + cc]           = acc[mt][nt][0];
            Hw[r0 * 33 + cc + 1]       = acc[mt][nt][1];
            Hw[(r0 + 8) * 33 + cc]     = acc[mt][nt][2];
            Hw[(r0 + 8) * 33 + cc + 1] = acc[mt][nt][3];
        }
    }
    __syncthreads();

    if (tid < MTILE && (m0 + tid) < NN) {
        float h[32];
#pragma unroll
        for (int k = 0; k < 32; k++) {
            float v = Hp[tid * 33 + k];                    // deterministic: warp 0..3
            v += Hp[1 * MTILE * 33 + tid * 33 + k];
            v += Hp[2 * MTILE * 33 + tid * 33 + k];
            v += Hp[3 * MTILE * 33 + tid * 33 + k];
            h[k] = v;
        }
        float4* o = (float4*)(g_Hp + ((size_t)khalf * NN + m0 + tid) * KO);
#pragma unroll
        for (int n4 = 0; n4 < 8; n4++)
            o[n4] = make_float4(h[n4*4], h[n4*4+1], h[n4*4+2], h[n4*4+3]);
    }
}

// ====== Kernel 2: combine K-halves, h2 = h @ W, BN partials (deterministic) ======
__global__ __launch_bounds__(128)
void k_combine(const float* __restrict__ W) {
    __shared__ float Ws[32 * 32];
    __shared__ float red[128 * 32];
    const int tid = threadIdx.x;
#pragma unroll
    for (int u = 0; u < 8; u++) Ws[tid + 128 * u] = W[tid + 128 * u];
    __syncthreads();

    const size_t row = (size_t)blockIdx.x * 128 + tid;
    float h2[32];
    if (row < NN) {
        const float4* p0 = (const float4*)(g_Hp + row * KO);
        const float4* p1 = (const float4*)(g_Hp + ((size_t)NN + row) * KO);
        float h[32];
#pragma unroll
        for (int q = 0; q < 8; q++) {
            float4 a = p0[q], b = p1[q];
            h[q*4+0] = a.x + b.x; h[q*4+1] = a.y + b.y;
            h[q*4+2] = a.z + b.z; h[q*4+3] = a.w + b.w;
        }
#pragma unroll
        for (int n = 0; n < 32; n++) {
            float s = 0.f;
#pragma unroll
            for (int k = 0; k < 32; k++) s += h[k] * Ws[k * 32 + n];
            h2[n] = s;
        }
        float4* o = (float4*)(g_H2 + row * KO);
#pragma unroll
        for (int q = 0; q < 8; q++)
            o[q] = make_float4(h2[q*4], h2[q*4+1], h2[q*4+2], h2[q*4+3]);
    } else {
#pragma unroll
        for (int n = 0; n < 32; n++) h2[n] = 0.f;
    }

#pragma unroll
    for (int n = 0; n < 32; n++) red[tid * 32 + n] = h2[n];
    __syncthreads();
    for (int st = 64; st > 0; st >>= 1) {
        if (tid < st) {
#pragma unroll
            for (int n = 0; n < 32; n++)
                red[tid * 32 + n] += red[(tid + st) * 32 + n];
        }
        __syncthreads();
    }
    if (tid < 32) g_part[blockIdx.x * KO + tid] = red[tid];
    __syncthreads();
#pragma unroll
    for (int n = 0; n < 32; n++) red[tid * 32 + n] = h2[n] * h2[n];
    __syncthreads();
    for (int st = 64; st > 0; st >>= 1) {
        if (tid < st) {
#pragma unroll
            for (int n = 0; n < 32; n++)
                red[tid * 32 + n] += red[(tid + st) * 32 + n];
        }
        __syncthreads();
    }
    if (tid < 32) g_psq[blockIdx.x * KO + tid] = red[tid];
}

// ========== Kernel 3: finalize BN stats (double, 8-way split, deterministic) ==========
__global__ void k_stats(const float* __restrict__ gamma,
                        const float* __restrict__ beta,
                        const float* __restrict__ bias) {
    __shared__ double sred[8][KO];
    __shared__ double qred[8][KO];
    const int c = threadIdx.x & 31;
    const int r = threadIdx.x >> 5;   // 0..7
    double s = 0.0, qq = 0.0;
    for (int b = r; b < SBLK; b += 8) {
        s  += (double)g_part[b * KO + c];
        qq += (double)g_psq [b * KO + c];
    }
    sred[r][c] = s; qred[r][c] = qq;
    __syncthreads();
    if (r == 0) {
        double ts = 0.0, tq = 0.0;
#pragma unroll
        for (int y = 0; y < 8; y++) { ts += sred[y][c]; tq += qred[y][c]; }
        double mean = ts / (double)NN;
        double var  = tq / (double)NN - mean * mean;
        double inv  = 1.0 / sqrt(var + 1e-5);
        double gsc  = (double)gamma[c] * inv;
        g_scale[c] = (float)gsc;
        g_shift[c] = (float)((double)beta[c] + (double)bias[c] - mean * gsc);
    }
}

// ================= Kernel 4: out = relu(H2*scale + shift) =================
__global__ void k_apply(float* __restrict__ out) {
    int idx4 = blockIdx.x * blockDim.x + threadIdx.x;
    float4 h  = *(const float4*)(g_H2 + (size_t)idx4 * 4);
    int cb    = (idx4 * 4) & 31;
    float4 sc = *(const float4*)(g_scale + cb);
    float4 sh = *(const float4*)(g_shift + cb);
    float4 o;
    o.x = fmaxf(h.x * sc.x + sh.x, 0.f);
    o.y = fmaxf(h.y * sc.y + sh.y, 0.f);
    o.z = fmaxf(h.z * sc.z + sh.z, 0.f);
    o.w = fmaxf(h.w * sc.w + sh.w, 0.f);
    *(float4*)(out + (size_t)idx4 * 4) = o;
}

// ================= launch =================
extern "C" void kernel_launch(void* const* d_in, const int* in_sizes, int n_in,
                              void* d_out, int out_size) {
    const float* A     = (const float*)d_in[0];
    const float* X     = (const float*)d_in[1];
    const float* W     = (const float*)d_in[2];
    const float* gamma = (const float*)d_in[3];
    const float* beta  = (const float*)d_in[4];
    const float* bias  = (const float*)d_in[5];
    float* out = (float*)d_out;

    cudaFuncSetAttribute(k_gemm1, cudaFuncAttributeMaxDynamicSharedMemorySize, SMEM_TOTAL);

    k_gemm1<<<dim3(GRIDM, 2), 128, SMEM_TOTAL>>>(A, X);
    k_combine<<<SBLK, 128>>>(W);
    k_stats<<<1, 256>>>(gamma, beta, bias);
    k_apply<<<(NN * KO / 4) / 256, 256>>>(out);
}